// round 1
// baseline (speedup 1.0000x reference)
#include <cuda_runtime.h>
#include <math.h>

// Problem constants
#define Bsz 8
#define Sq  2048
#define Dm  256
#define Hh  4
#define Dk  64
#define NTOK (Bsz*Sq)          // 16384
#define OUT0_ELEMS ((size_t)NTOK*Dm) // 4194304

// ---------------- scratch (static device globals; allocation-free contract) ---
__device__ float g_Q[(size_t)Bsz*Hh*Sq*Dk];   // (b,h,q,d) 16MB
__device__ float g_K[(size_t)Bsz*Hh*Sq*Dk];   // 16MB
__device__ float g_V[(size_t)NTOK*Dm];        // 16MB
__device__ float g_S[(size_t)Bsz*Hh*Sq*Sq];   // raw scores, 512MiB
__device__ float g_O[(size_t)NTOK*Dm];        // attn output pre-proj, 16MB

// =============================================================================
// Generic 128x128x16 SGEMM, 256 threads, 8x8 microtile (4+4 split for
// conflict-free float4 smem reads). All dims assumed divisible (true here).
// OUTMODE 0: C row-major (ldc). OUTMODE 1: Q/K head-major scatter:
//   row=token -> (b,q); col=n -> (h,d); C[((b*H+h)*S+q)*64+d]
// =============================================================================
template<bool TRANSB, int OUTMODE>
__global__ void __launch_bounds__(256) sgemm_kernel(
    const float* __restrict__ A, const float* __restrict__ Bm,
    float* __restrict__ C, const float* __restrict__ bias,
    int M, int N, int K, int lda, int ldb, int ldc,
    long long aStride, long long bStride, long long cStride, float alpha)
{
    constexpr int BM = 128, BN = 128, BK = 16;
    __shared__ float As[BK][132];
    __shared__ float Bs[BK][132];

    const int z = blockIdx.z;
    A  += (size_t)z * aStride;
    Bm += (size_t)z * bStride;
    C  += (size_t)z * cStride;

    const int bm = blockIdx.y * BM;
    const int bn = blockIdx.x * BN;
    const int tid = threadIdx.x;
    const int tx = tid & 15;
    const int ty = tid >> 4;

    float acc[8][8];
#pragma unroll
    for (int i = 0; i < 8; i++)
#pragma unroll
        for (int j = 0; j < 8; j++) acc[i][j] = 0.f;

    const int nk = K / BK;
    for (int kt = 0; kt < nk; ++kt) {
        // ---- A tile: BM x BK, store transposed As[k][m]
#pragma unroll
        for (int r = 0; r < 2; ++r) {
            int lin = tid + r * 256;          // 0..511
            int row = lin >> 2;               // 0..127
            int c4  = (lin & 3) * 4;          // 0,4,8,12
            float4 v = *(const float4*)&A[(size_t)(bm + row) * lda + kt * BK + c4];
            As[c4 + 0][row] = v.x; As[c4 + 1][row] = v.y;
            As[c4 + 2][row] = v.z; As[c4 + 3][row] = v.w;
        }
        // ---- B tile
        if (!TRANSB) {
#pragma unroll
            for (int r = 0; r < 2; ++r) {
                int lin  = tid + r * 256;
                int rowk = lin >> 5;          // 0..15
                int c4   = (lin & 31) * 4;    // 0..124
                float4 v = *(const float4*)&Bm[(size_t)(kt * BK + rowk) * ldb + bn + c4];
                *(float4*)&Bs[rowk][c4] = v;
            }
        } else {
#pragma unroll
            for (int r = 0; r < 2; ++r) {
                int lin = tid + r * 256;
                int row = lin >> 2;           // n index 0..127
                int c4  = (lin & 3) * 4;      // k index
                float4 v = *(const float4*)&Bm[(size_t)(bn + row) * ldb + kt * BK + c4];
                Bs[c4 + 0][row] = v.x; Bs[c4 + 1][row] = v.y;
                Bs[c4 + 2][row] = v.z; Bs[c4 + 3][row] = v.w;
            }
        }
        __syncthreads();

#pragma unroll
        for (int kk = 0; kk < BK; ++kk) {
            float4 a0 = *(const float4*)&As[kk][ty * 4];
            float4 a1 = *(const float4*)&As[kk][64 + ty * 4];
            float4 b0 = *(const float4*)&Bs[kk][tx * 4];
            float4 b1 = *(const float4*)&Bs[kk][64 + tx * 4];
            float ar[8] = {a0.x, a0.y, a0.z, a0.w, a1.x, a1.y, a1.z, a1.w};
            float br[8] = {b0.x, b0.y, b0.z, b0.w, b1.x, b1.y, b1.z, b1.w};
#pragma unroll
            for (int i = 0; i < 8; i++)
#pragma unroll
                for (int j = 0; j < 8; j++)
                    acc[i][j] = fmaf(ar[i], br[j], acc[i][j]);
        }
        __syncthreads();
    }

    // ---- writeback (two 4-wide column chunks per row)
#pragma unroll
    for (int i = 0; i < 8; i++) {
        int row = bm + ((i < 4) ? (ty * 4 + i) : (64 + ty * 4 + (i - 4)));
#pragma unroll
        for (int jb = 0; jb < 2; jb++) {
            int col = bn + ((jb == 0) ? (tx * 4) : (64 + tx * 4));
            float4 v;
            v.x = acc[i][jb * 4 + 0] * alpha;
            v.y = acc[i][jb * 4 + 1] * alpha;
            v.z = acc[i][jb * 4 + 2] * alpha;
            v.w = acc[i][jb * 4 + 3] * alpha;
            if (bias) {
                v.x += bias[col + 0]; v.y += bias[col + 1];
                v.z += bias[col + 2]; v.w += bias[col + 3];
            }
            if (OUTMODE == 0) {
                *(float4*)&C[(size_t)row * ldc + col] = v;
            } else {
                int b = row >> 11, q = row & 2047;
                int h = col >> 6,  d = col & 63;
                *(float4*)&C[((size_t)((b * Hh + h) * Sq) + q) * Dk + d] = v;
            }
        }
    }
}

// =============================================================================
// Fused per-row softmax over 4 heads + head-average.
// One block per (b,q): loads 4 score rows (4x2048 fp32 = 32KB) to smem,
// per-head max/sum-exp reductions, writes avg_attn row into d_out region 2.
// =============================================================================
__device__ __forceinline__ float warp_max(float v) {
#pragma unroll
    for (int o = 16; o; o >>= 1) v = fmaxf(v, __shfl_xor_sync(0xffffffffu, v, o));
    return v;
}
__device__ __forceinline__ float warp_sum(float v) {
#pragma unroll
    for (int o = 16; o; o >>= 1) v += __shfl_xor_sync(0xffffffffu, v, o);
    return v;
}

__global__ void __launch_bounds__(256) softmax_avg_kernel(float* __restrict__ avg)
{
    const int q = blockIdx.x;
    const int b = blockIdx.y;
    __shared__ float sh[Hh][Sq];   // 32KB
    __shared__ float red[8];

    const int tid  = threadIdx.x;
    const int lane = tid & 31;
    const int wid  = tid >> 5;

    float rz[Hh];

#pragma unroll
    for (int h = 0; h < Hh; ++h) {
        const float* srow = &g_S[(((size_t)(b * Hh + h)) * Sq + q) * Sq];
        float lmax = -1e30f;
        for (int k = tid * 4; k < Sq; k += 1024) {
            float4 v = *(const float4*)&srow[k];
            sh[h][k + 0] = v.x; sh[h][k + 1] = v.y;
            sh[h][k + 2] = v.z; sh[h][k + 3] = v.w;
            lmax = fmaxf(lmax, fmaxf(fmaxf(v.x, v.y), fmaxf(v.z, v.w)));
        }
        // block max
        float wm = warp_max(lmax);
        if (lane == 0) red[wid] = wm;
        __syncthreads();
        float m = red[0];
#pragma unroll
        for (int i = 1; i < 8; i++) m = fmaxf(m, red[i]);
        __syncthreads();
        // exp in place + sum
        float lsum = 0.f;
        for (int k = tid * 4; k < Sq; k += 1024) {
            float e0 = __expf(sh[h][k + 0] - m);
            float e1 = __expf(sh[h][k + 1] - m);
            float e2 = __expf(sh[h][k + 2] - m);
            float e3 = __expf(sh[h][k + 3] - m);
            sh[h][k + 0] = e0; sh[h][k + 1] = e1;
            sh[h][k + 2] = e2; sh[h][k + 3] = e3;
            lsum += (e0 + e1) + (e2 + e3);
        }
        float ws = warp_sum(lsum);
        if (lane == 0) red[wid] = ws;
        __syncthreads();
        float zt = red[0];
#pragma unroll
        for (int i = 1; i < 8; i++) zt += red[i];
        __syncthreads();
        rz[h] = 1.f / zt;
    }

    float* orow = &avg[((size_t)b * Sq + q) * Sq];
    for (int k = tid * 4; k < Sq; k += 1024) {
        float4 r;
        r.x = 0.25f * (sh[0][k + 0] * rz[0] + sh[1][k + 0] * rz[1] +
                       sh[2][k + 0] * rz[2] + sh[3][k + 0] * rz[3]);
        r.y = 0.25f * (sh[0][k + 1] * rz[0] + sh[1][k + 1] * rz[1] +
                       sh[2][k + 1] * rz[2] + sh[3][k + 1] * rz[3]);
        r.z = 0.25f * (sh[0][k + 2] * rz[0] + sh[1][k + 2] * rz[1] +
                       sh[2][k + 2] * rz[2] + sh[3][k + 2] * rz[3]);
        r.w = 0.25f * (sh[0][k + 3] * rz[0] + sh[1][k + 3] * rz[1] +
                       sh[2][k + 3] * rz[2] + sh[3][k + 3] * rz[3]);
        *(float4*)&orow[k] = r;
    }
}

// =============================================================================
// Launch
// =============================================================================
extern "C" void kernel_launch(void* const* d_in, const int* in_sizes, int n_in,
                              void* d_out, int out_size)
{
    (void)in_sizes; (void)n_in; (void)out_size;
    const float* query = (const float*)d_in[0];
    const float* key   = (const float*)d_in[1];
    const float* value = (const float*)d_in[2];
    const float* W_q   = (const float*)d_in[3];
    const float* b_q   = (const float*)d_in[4];
    const float* W_k   = (const float*)d_in[5];
    const float* b_k   = (const float*)d_in[6];
    const float* W_v   = (const float*)d_in[7];
    const float* b_v   = (const float*)d_in[8];
    const float* W_o   = (const float*)d_in[9];
    const float* b_o   = (const float*)d_in[10];

    float* out = (float*)d_out;                 // (B,S,D)
    float* avg = out + OUT0_ELEMS;              // (B,S,S)

    float *pQ, *pK, *pV, *pS, *pO;
    cudaGetSymbolAddress((void**)&pQ, g_Q);
    cudaGetSymbolAddress((void**)&pK, g_K);
    cudaGetSymbolAddress((void**)&pV, g_V);
    cudaGetSymbolAddress((void**)&pS, g_S);
    cudaGetSymbolAddress((void**)&pO, g_O);

    dim3 blk(256);

    // 1-3: input projections (M=16384, N=256, K=256)
    {
        dim3 grid(Dm / 128, NTOK / 128, 1);
        sgemm_kernel<false, 1><<<grid, blk>>>(query, W_q, pQ, b_q,
            NTOK, Dm, Dm, Dm, Dm, Dm, 0, 0, 0, 1.0f);
        sgemm_kernel<false, 1><<<grid, blk>>>(key, W_k, pK, b_k,
            NTOK, Dm, Dm, Dm, Dm, Dm, 0, 0, 0, 1.0f);
        sgemm_kernel<false, 0><<<grid, blk>>>(value, W_v, pV, b_v,
            NTOK, Dm, Dm, Dm, Dm, Dm, 0, 0, 0, 1.0f);
    }

    // 4: scores S = (1/8) * Q @ K^T per (b,h)  (M=N=2048, K=64, 32 batches)
    {
        dim3 grid(Sq / 128, Sq / 128, Bsz * Hh);
        sgemm_kernel<true, 0><<<grid, blk>>>(pQ, pK, pS, nullptr,
            Sq, Sq, Dk, Dk, Dk, Sq,
            (long long)Sq * Dk, (long long)Sq * Dk, (long long)Sq * Sq, 0.125f);
    }

    // 5: softmax per head + average over heads -> avg_attn (in d_out)
    {
        dim3 grid(Sq, Bsz, 1);
        softmax_avg_kernel<<<grid, blk>>>(avg);
    }

    // 6: out_pre = avg_attn @ V per batch (M=2048, N=256, K=2048, 8 batches)
    {
        dim3 grid(Dm / 128, Sq / 128, Bsz);
        sgemm_kernel<false, 0><<<grid, blk>>>(avg, pV, pO, nullptr,
            Sq, Dm, Sq, Sq, Dm, Dm,
            (long long)Sq * Sq, (long long)Sq * Dm, (long long)Sq * Dm, 1.0f);
    }

    // 7: final projection out = out_pre @ W_o + b_o
    {
        dim3 grid(Dm / 128, NTOK / 128, 1);
        sgemm_kernel<false, 0><<<grid, blk>>>(pO, W_o, out, b_o,
            NTOK, Dm, Dm, Dm, Dm, Dm, 0, 0, 0, 1.0f);
    }
}

// round 2
// speedup vs baseline: 2.5997x; 2.5997x over previous
#include <cuda_runtime.h>
#include <math.h>

// Problem constants
#define Bsz 8
#define Sq  2048
#define Dm  256
#define Hh  4
#define Dk  64
#define NTOK (Bsz*Sq)          // 16384
#define OUT0_ELEMS ((size_t)NTOK*Dm) // 4194304

// ---------------- scratch (static device globals; allocation-free contract) ---
__device__ float g_Q[(size_t)Bsz*Hh*Sq*Dk];   // (b,h,q,d) 16MB
__device__ float g_K[(size_t)Bsz*Hh*Sq*Dk];   // 16MB
__device__ float g_V[(size_t)NTOK*Dm];        // 16MB
__device__ float g_S[(size_t)Bsz*Hh*Sq*Sq];   // raw scores, 512MiB
__device__ float g_O[(size_t)NTOK*Dm];        // attn output pre-proj, 16MB

// =============================================================================
// tf32 mma helpers
// =============================================================================
__device__ __forceinline__ unsigned f2tf(float f) {
    unsigned u;
    asm("cvt.rna.tf32.f32 %0, %1;" : "=r"(u) : "f"(f));
    return u;
}
__device__ __forceinline__ void mma_tf32(float c[4],
    unsigned a0, unsigned a1, unsigned a2, unsigned a3,
    unsigned b0, unsigned b1)
{
    asm volatile(
        "mma.sync.aligned.m16n8k8.row.col.f32.tf32.tf32.f32 "
        "{%0,%1,%2,%3},{%4,%5,%6,%7},{%8,%9},{%0,%1,%2,%3};"
        : "+f"(c[0]), "+f"(c[1]), "+f"(c[2]), "+f"(c[3])
        : "r"(a0), "r"(a1), "r"(a2), "r"(a3), "r"(b0), "r"(b1));
}

// =============================================================================
// Scores kernel (tensor): S = (1/8) * Q @ K^T per (b,h).
// M=N=2048, K=64. Tile 128x128, K fits entirely in smem (no k-loop staging).
// 256 thr = 8 warps (2 M x 4 N), warp tile 64x32, m16n8k8 tf32.
// Dynamic smem: Qs[128][68] + Ks[128][68] tf32 (69632 B).
// =============================================================================
__global__ void __launch_bounds__(256, 2) scores_tc_kernel(
    const float* __restrict__ Q, const float* __restrict__ K,
    float* __restrict__ S)
{
    extern __shared__ unsigned dynsmem[];
    unsigned (*Qs)[68] = (unsigned(*)[68])dynsmem;
    unsigned (*Ks)[68] = (unsigned(*)[68])(dynsmem + 128 * 68);

    const int tid  = threadIdx.x;
    const int lane = tid & 31;
    const int wid  = tid >> 5;
    const int g = lane >> 2, t = lane & 3;
    const int m0 = (wid & 1) * 64;
    const int n0 = (wid >> 1) * 32;

    const float* Qb = Q + (size_t)blockIdx.z * Sq * Dk + (size_t)blockIdx.y * 128 * Dk;
    const float* Kb = K + (size_t)blockIdx.z * Sq * Dk + (size_t)blockIdx.x * 128 * Dk;

    // load 128x64 Q and K tiles, cvt to tf32
#pragma unroll
    for (int i = 0; i < 8; ++i) {
        int idx = i * 256 + tid;          // 0..2047 float4 units
        int row = idx >> 4;               // 16 float4 per row
        int c4  = (idx & 15) * 4;
        float4 q = *(const float4*)&Qb[(size_t)row * Dk + c4];
        uint4 uq = { f2tf(q.x), f2tf(q.y), f2tf(q.z), f2tf(q.w) };
        *(uint4*)&Qs[row][c4] = uq;
        float4 k = *(const float4*)&Kb[(size_t)row * Dk + c4];
        uint4 uk = { f2tf(k.x), f2tf(k.y), f2tf(k.z), f2tf(k.w) };
        *(uint4*)&Ks[row][c4] = uk;
    }
    __syncthreads();

    float acc[4][4][4];
#pragma unroll
    for (int mi = 0; mi < 4; mi++)
#pragma unroll
        for (int ni = 0; ni < 4; ni++)
#pragma unroll
            for (int r = 0; r < 4; r++) acc[mi][ni][r] = 0.f;

#pragma unroll
    for (int ks = 0; ks < 8; ++ks) {
        const int kb = ks * 8;
        unsigned a[4][4], b[4][2];
#pragma unroll
        for (int mi = 0; mi < 4; mi++) {
            int r = m0 + mi * 16 + g;
            a[mi][0] = Qs[r][kb + t];
            a[mi][1] = Qs[r + 8][kb + t];
            a[mi][2] = Qs[r][kb + 4 + t];
            a[mi][3] = Qs[r + 8][kb + 4 + t];
        }
#pragma unroll
        for (int ni = 0; ni < 4; ni++) {
            int cn = n0 + ni * 8 + g;
            b[ni][0] = Ks[cn][kb + t];
            b[ni][1] = Ks[cn][kb + 4 + t];
        }
#pragma unroll
        for (int mi = 0; mi < 4; mi++)
#pragma unroll
            for (int ni = 0; ni < 4; ni++)
                mma_tf32(acc[mi][ni], a[mi][0], a[mi][1], a[mi][2], a[mi][3],
                         b[ni][0], b[ni][1]);
    }

    // epilogue: alpha = 1/8
    float* Sb = S + (size_t)blockIdx.z * Sq * Sq;
    const int rbase = blockIdx.y * 128 + m0;
    const int cbase = blockIdx.x * 128 + n0;
#pragma unroll
    for (int mi = 0; mi < 4; mi++) {
#pragma unroll
        for (int ni = 0; ni < 4; ni++) {
            int r = rbase + mi * 16 + g;
            int c = cbase + ni * 8 + 2 * t;
            float2 v0 = { acc[mi][ni][0] * 0.125f, acc[mi][ni][1] * 0.125f };
            float2 v1 = { acc[mi][ni][2] * 0.125f, acc[mi][ni][3] * 0.125f };
            *(float2*)&Sb[(size_t)r * Sq + c]       = v0;
            *(float2*)&Sb[(size_t)(r + 8) * Sq + c] = v1;
        }
    }
}

// =============================================================================
// avg @ V kernel (tensor): per batch, M=2048, N=256, K=2048.
// Tile 128x128x16, double-buffered smem, 256 thr (2x4 warps), warp 64x32.
// =============================================================================
__global__ void __launch_bounds__(256, 2) avgv_tc_kernel(
    const float* __restrict__ A, const float* __restrict__ B,
    float* __restrict__ C)
{
    __shared__ unsigned As[2][128][20];
    __shared__ unsigned Bs[2][16][132];

    const int tid  = threadIdx.x;
    const int lane = tid & 31;
    const int wid  = tid >> 5;
    const int g = lane >> 2, t = lane & 3;
    const int m0 = (wid & 1) * 64;
    const int n0 = (wid >> 1) * 32;

    const float* Ab = A + (size_t)blockIdx.z * Sq * Sq + (size_t)blockIdx.y * 128 * Sq;
    const float* Bb = B + (size_t)blockIdx.z * Sq * Dm + blockIdx.x * 128;
    float*       Cb = C + (size_t)blockIdx.z * Sq * Dm;

    // A-tile load indices: 128x16 floats = 512 float4, 2 per thread
    const int arow0 = tid >> 2;              // +64 for second
    const int ac4   = (tid & 3) * 4;
    // B-tile: 16x128 floats = 512 float4, 2 per thread
    const int brow0 = tid >> 5;              // +8 for second
    const int bc4   = (tid & 31) * 4;

    float4 pa0, pa1, pb0, pb1;

    auto load_regs = [&](int kt) {
        pa0 = *(const float4*)&Ab[(size_t)arow0 * Sq + kt * 16 + ac4];
        pa1 = *(const float4*)&Ab[(size_t)(arow0 + 64) * Sq + kt * 16 + ac4];
        pb0 = *(const float4*)&Bb[(size_t)(kt * 16 + brow0) * Dm + bc4];
        pb1 = *(const float4*)&Bb[(size_t)(kt * 16 + brow0 + 8) * Dm + bc4];
    };
    auto store_smem = [&](int buf) {
        uint4 u;
        u.x = f2tf(pa0.x); u.y = f2tf(pa0.y); u.z = f2tf(pa0.z); u.w = f2tf(pa0.w);
        *(uint4*)&As[buf][arow0][ac4] = u;
        u.x = f2tf(pa1.x); u.y = f2tf(pa1.y); u.z = f2tf(pa1.z); u.w = f2tf(pa1.w);
        *(uint4*)&As[buf][arow0 + 64][ac4] = u;
        u.x = f2tf(pb0.x); u.y = f2tf(pb0.y); u.z = f2tf(pb0.z); u.w = f2tf(pb0.w);
        *(uint4*)&Bs[buf][brow0][bc4] = u;
        u.x = f2tf(pb1.x); u.y = f2tf(pb1.y); u.z = f2tf(pb1.z); u.w = f2tf(pb1.w);
        *(uint4*)&Bs[buf][brow0 + 8][bc4] = u;
    };

    float acc[4][4][4];
#pragma unroll
    for (int mi = 0; mi < 4; mi++)
#pragma unroll
        for (int ni = 0; ni < 4; ni++)
#pragma unroll
            for (int r = 0; r < 4; r++) acc[mi][ni][r] = 0.f;

    load_regs(0);
    store_smem(0);
    __syncthreads();

    const int NKT = Sq / 16;   // 128
    for (int kt = 0; kt < NKT; ++kt) {
        int buf = kt & 1;
        if (kt + 1 < NKT) load_regs(kt + 1);

#pragma unroll
        for (int ks = 0; ks < 2; ++ks) {
            const int kb = ks * 8;
            unsigned a[4][4], b[4][2];
#pragma unroll
            for (int mi = 0; mi < 4; mi++) {
                int r = m0 + mi * 16 + g;
                a[mi][0] = As[buf][r][kb + t];
                a[mi][1] = As[buf][r + 8][kb + t];
                a[mi][2] = As[buf][r][kb + 4 + t];
                a[mi][3] = As[buf][r + 8][kb + 4 + t];
            }
#pragma unroll
            for (int ni = 0; ni < 4; ni++) {
                int cn = n0 + ni * 8 + g;
                b[ni][0] = Bs[buf][kb + t][cn];
                b[ni][1] = Bs[buf][kb + 4 + t][cn];
            }
#pragma unroll
            for (int mi = 0; mi < 4; mi++)
#pragma unroll
                for (int ni = 0; ni < 4; ni++)
                    mma_tf32(acc[mi][ni], a[mi][0], a[mi][1], a[mi][2], a[mi][3],
                             b[ni][0], b[ni][1]);
        }

        if (kt + 1 < NKT) store_smem(buf ^ 1);
        __syncthreads();
    }

    const int rbase = blockIdx.y * 128 + m0;
    const int cbase = blockIdx.x * 128 + n0;
#pragma unroll
    for (int mi = 0; mi < 4; mi++) {
#pragma unroll
        for (int ni = 0; ni < 4; ni++) {
            int r = rbase + mi * 16 + g;
            int c = cbase + ni * 8 + 2 * t;
            float2 v0 = { acc[mi][ni][0], acc[mi][ni][1] };
            float2 v1 = { acc[mi][ni][2], acc[mi][ni][3] };
            *(float2*)&Cb[(size_t)r * Dm + c]       = v0;
            *(float2*)&Cb[(size_t)(r + 8) * Dm + c] = v1;
        }
    }
}

// =============================================================================
// Generic 128x128x16 fp32 SGEMM (projections + final proj; accuracy-critical).
// OUTMODE 0: C row-major. OUTMODE 1: head-major scatter for Q/K.
// =============================================================================
template<bool TRANSB, int OUTMODE>
__global__ void __launch_bounds__(256) sgemm_kernel(
    const float* __restrict__ A, const float* __restrict__ Bm,
    float* __restrict__ C, const float* __restrict__ bias,
    int M, int N, int K, int lda, int ldb, int ldc,
    long long aStride, long long bStride, long long cStride, float alpha)
{
    constexpr int BM = 128, BN = 128, BK = 16;
    __shared__ float As[BK][132];
    __shared__ float Bs[BK][132];

    const int z = blockIdx.z;
    A  += (size_t)z * aStride;
    Bm += (size_t)z * bStride;
    C  += (size_t)z * cStride;

    const int bm = blockIdx.y * BM;
    const int bn = blockIdx.x * BN;
    const int tid = threadIdx.x;
    const int tx = tid & 15;
    const int ty = tid >> 4;

    float acc[8][8];
#pragma unroll
    for (int i = 0; i < 8; i++)
#pragma unroll
        for (int j = 0; j < 8; j++) acc[i][j] = 0.f;

    const int nk = K / BK;
    for (int kt = 0; kt < nk; ++kt) {
#pragma unroll
        for (int r = 0; r < 2; ++r) {
            int lin = tid + r * 256;
            int row = lin >> 2;
            int c4  = (lin & 3) * 4;
            float4 v = *(const float4*)&A[(size_t)(bm + row) * lda + kt * BK + c4];
            As[c4 + 0][row] = v.x; As[c4 + 1][row] = v.y;
            As[c4 + 2][row] = v.z; As[c4 + 3][row] = v.w;
        }
        if (!TRANSB) {
#pragma unroll
            for (int r = 0; r < 2; ++r) {
                int lin  = tid + r * 256;
                int rowk = lin >> 5;
                int c4   = (lin & 31) * 4;
                float4 v = *(const float4*)&Bm[(size_t)(kt * BK + rowk) * ldb + bn + c4];
                *(float4*)&Bs[rowk][c4] = v;
            }
        } else {
#pragma unroll
            for (int r = 0; r < 2; ++r) {
                int lin = tid + r * 256;
                int row = lin >> 2;
                int c4  = (lin & 3) * 4;
                float4 v = *(const float4*)&Bm[(size_t)(bn + row) * ldb + kt * BK + c4];
                Bs[c4 + 0][row] = v.x; Bs[c4 + 1][row] = v.y;
                Bs[c4 + 2][row] = v.z; Bs[c4 + 3][row] = v.w;
            }
        }
        __syncthreads();

#pragma unroll
        for (int kk = 0; kk < BK; ++kk) {
            float4 a0 = *(const float4*)&As[kk][ty * 4];
            float4 a1 = *(const float4*)&As[kk][64 + ty * 4];
            float4 b0 = *(const float4*)&Bs[kk][tx * 4];
            float4 b1 = *(const float4*)&Bs[kk][64 + tx * 4];
            float ar[8] = {a0.x, a0.y, a0.z, a0.w, a1.x, a1.y, a1.z, a1.w};
            float br[8] = {b0.x, b0.y, b0.z, b0.w, b1.x, b1.y, b1.z, b1.w};
#pragma unroll
            for (int i = 0; i < 8; i++)
#pragma unroll
                for (int j = 0; j < 8; j++)
                    acc[i][j] = fmaf(ar[i], br[j], acc[i][j]);
        }
        __syncthreads();
    }

#pragma unroll
    for (int i = 0; i < 8; i++) {
        int row = bm + ((i < 4) ? (ty * 4 + i) : (64 + ty * 4 + (i - 4)));
#pragma unroll
        for (int jb = 0; jb < 2; jb++) {
            int col = bn + ((jb == 0) ? (tx * 4) : (64 + tx * 4));
            float4 v;
            v.x = acc[i][jb * 4 + 0] * alpha;
            v.y = acc[i][jb * 4 + 1] * alpha;
            v.z = acc[i][jb * 4 + 2] * alpha;
            v.w = acc[i][jb * 4 + 3] * alpha;
            if (bias) {
                v.x += bias[col + 0]; v.y += bias[col + 1];
                v.z += bias[col + 2]; v.w += bias[col + 3];
            }
            if (OUTMODE == 0) {
                *(float4*)&C[(size_t)row * ldc + col] = v;
            } else {
                int b = row >> 11, q = row & 2047;
                int h = col >> 6,  d = col & 63;
                *(float4*)&C[((size_t)((b * Hh + h) * Sq) + q) * Dk + d] = v;
            }
        }
    }
}

// =============================================================================
// Fused per-row softmax over 4 heads + head-average.
// =============================================================================
__device__ __forceinline__ float warp_max(float v) {
#pragma unroll
    for (int o = 16; o; o >>= 1) v = fmaxf(v, __shfl_xor_sync(0xffffffffu, v, o));
    return v;
}
__device__ __forceinline__ float warp_sum(float v) {
#pragma unroll
    for (int o = 16; o; o >>= 1) v += __shfl_xor_sync(0xffffffffu, v, o);
    return v;
}

__global__ void __launch_bounds__(256) softmax_avg_kernel(float* __restrict__ avg)
{
    const int q = blockIdx.x;
    const int b = blockIdx.y;
    __shared__ float sh[Hh][Sq];   // 32KB
    __shared__ float red[8];

    const int tid  = threadIdx.x;
    const int lane = tid & 31;
    const int wid  = tid >> 5;

    float rz[Hh];

#pragma unroll
    for (int h = 0; h < Hh; ++h) {
        const float* srow = &g_S[(((size_t)(b * Hh + h)) * Sq + q) * Sq];
        float lmax = -1e30f;
        for (int k = tid * 4; k < Sq; k += 1024) {
            float4 v = *(const float4*)&srow[k];
            sh[h][k + 0] = v.x; sh[h][k + 1] = v.y;
            sh[h][k + 2] = v.z; sh[h][k + 3] = v.w;
            lmax = fmaxf(lmax, fmaxf(fmaxf(v.x, v.y), fmaxf(v.z, v.w)));
        }
        float wm = warp_max(lmax);
        if (lane == 0) red[wid] = wm;
        __syncthreads();
        float m = red[0];
#pragma unroll
        for (int i = 1; i < 8; i++) m = fmaxf(m, red[i]);
        __syncthreads();
        float lsum = 0.f;
        for (int k = tid * 4; k < Sq; k += 1024) {
            float e0 = __expf(sh[h][k + 0] - m);
            float e1 = __expf(sh[h][k + 1] - m);
            float e2 = __expf(sh[h][k + 2] - m);
            float e3 = __expf(sh[h][k + 3] - m);
            sh[h][k + 0] = e0; sh[h][k + 1] = e1;
            sh[h][k + 2] = e2; sh[h][k + 3] = e3;
            lsum += (e0 + e1) + (e2 + e3);
        }
        float ws = warp_sum(lsum);
        if (lane == 0) red[wid] = ws;
        __syncthreads();
        float zt = red[0];
#pragma unroll
        for (int i = 1; i < 8; i++) zt += red[i];
        __syncthreads();
        rz[h] = 1.f / zt;
    }

    float* orow = &avg[((size_t)b * Sq + q) * Sq];
    for (int k = tid * 4; k < Sq; k += 1024) {
        float4 r;
        r.x = 0.25f * (sh[0][k + 0] * rz[0] + sh[1][k + 0] * rz[1] +
                       sh[2][k + 0] * rz[2] + sh[3][k + 0] * rz[3]);
        r.y = 0.25f * (sh[0][k + 1] * rz[0] + sh[1][k + 1] * rz[1] +
                       sh[2][k + 1] * rz[2] + sh[3][k + 1] * rz[3]);
        r.z = 0.25f * (sh[0][k + 2] * rz[0] + sh[1][k + 2] * rz[1] +
                       sh[2][k + 2] * rz[2] + sh[3][k + 2] * rz[3]);
        r.w = 0.25f * (sh[0][k + 3] * rz[0] + sh[1][k + 3] * rz[1] +
                       sh[2][k + 3] * rz[2] + sh[3][k + 3] * rz[3]);
        *(float4*)&orow[k] = r;
    }
}

// =============================================================================
// Launch
// =============================================================================
extern "C" void kernel_launch(void* const* d_in, const int* in_sizes, int n_in,
                              void* d_out, int out_size)
{
    (void)in_sizes; (void)n_in; (void)out_size;
    const float* query = (const float*)d_in[0];
    const float* key   = (const float*)d_in[1];
    const float* value = (const float*)d_in[2];
    const float* W_q   = (const float*)d_in[3];
    const float* b_q   = (const float*)d_in[4];
    const float* W_k   = (const float*)d_in[5];
    const float* b_k   = (const float*)d_in[6];
    const float* W_v   = (const float*)d_in[7];
    const float* b_v   = (const float*)d_in[8];
    const float* W_o   = (const float*)d_in[9];
    const float* b_o   = (const float*)d_in[10];

    float* out = (float*)d_out;                 // (B,S,D)
    float* avg = out + OUT0_ELEMS;              // (B,S,S)

    float *pQ, *pK, *pV, *pS, *pO;
    cudaGetSymbolAddress((void**)&pQ, g_Q);
    cudaGetSymbolAddress((void**)&pK, g_K);
    cudaGetSymbolAddress((void**)&pV, g_V);
    cudaGetSymbolAddress((void**)&pS, g_S);
    cudaGetSymbolAddress((void**)&pO, g_O);

    dim3 blk(256);

    // 1-3: input projections (fp32 SIMT — accuracy-critical feeders)
    {
        dim3 grid(Dm / 128, NTOK / 128, 1);
        sgemm_kernel<false, 1><<<grid, blk>>>(query, W_q, pQ, b_q,
            NTOK, Dm, Dm, Dm, Dm, Dm, 0, 0, 0, 1.0f);
        sgemm_kernel<false, 1><<<grid, blk>>>(key, W_k, pK, b_k,
            NTOK, Dm, Dm, Dm, Dm, Dm, 0, 0, 0, 1.0f);
        sgemm_kernel<false, 0><<<grid, blk>>>(value, W_v, pV, b_v,
            NTOK, Dm, Dm, Dm, Dm, Dm, 0, 0, 0, 1.0f);
    }

    // 4: scores S = (1/8) * Q @ K^T per (b,h)  — TF32 tensor cores
    {
        const int smem = 2 * 128 * 68 * 4;   // 69632 B
        cudaFuncSetAttribute(scores_tc_kernel,
            cudaFuncAttributeMaxDynamicSharedMemorySize, smem);
        dim3 grid(Sq / 128, Sq / 128, Bsz * Hh);
        scores_tc_kernel<<<grid, blk, smem>>>(pQ, pK, pS);
    }

    // 5: softmax per head + average over heads -> avg_attn (in d_out)
    {
        dim3 grid(Sq, Bsz, 1);
        softmax_avg_kernel<<<grid, blk>>>(avg);
    }

    // 6: out_pre = avg_attn @ V per batch — TF32 tensor cores
    {
        dim3 grid(Dm / 128, Sq / 128, Bsz);
        avgv_tc_kernel<<<grid, blk>>>(avg, pV, pO);
    }

    // 7: final projection out = out_pre @ W_o + b_o (fp32 SIMT)
    {
        dim3 grid(Dm / 128, NTOK / 128, 1);
        sgemm_kernel<false, 0><<<grid, blk>>>(pO, W_o, out, b_o,
            NTOK, Dm, Dm, Dm, Dm, Dm, 0, 0, 0, 1.0f);
    }
}

// round 3
// speedup vs baseline: 3.4083x; 1.3110x over previous
#include <cuda_runtime.h>
#include <math.h>

// Problem constants
#define Bsz 8
#define Sq  2048
#define Dm  256
#define Hh  4
#define Dk  64
#define NTOK (Bsz*Sq)          // 16384
#define OUT0_ELEMS ((size_t)NTOK*Dm) // 4194304

// ---------------- scratch (static device globals; allocation-free contract) ---
__device__ float g_Q[(size_t)Bsz*Hh*Sq*Dk];   // (b,h,q,d) 16MB
__device__ float g_K[(size_t)Bsz*Hh*Sq*Dk];   // 16MB
__device__ float g_V[(size_t)NTOK*Dm];        // 16MB
__device__ float g_S[(size_t)Bsz*Hh*Sq*Sq];   // raw scores, 512MiB
__device__ float g_O[(size_t)NTOK*Dm];        // attn output pre-proj, 16MB

// =============================================================================
// helpers
// =============================================================================
__device__ __forceinline__ unsigned f2tf(float f) {
    unsigned u;
    asm("cvt.rna.tf32.f32 %0, %1;" : "=r"(u) : "f"(f));
    return u;
}
__device__ __forceinline__ void mma_tf32(float c[4],
    unsigned a0, unsigned a1, unsigned a2, unsigned a3,
    unsigned b0, unsigned b1)
{
    asm volatile(
        "mma.sync.aligned.m16n8k8.row.col.f32.tf32.tf32.f32 "
        "{%0,%1,%2,%3},{%4,%5,%6,%7},{%8,%9},{%0,%1,%2,%3};"
        : "+f"(c[0]), "+f"(c[1]), "+f"(c[2]), "+f"(c[3])
        : "r"(a0), "r"(a1), "r"(a2), "r"(a3), "r"(b0), "r"(b1));
}
__device__ __forceinline__ void cp_async16(void* smem, const void* gmem) {
    unsigned saddr = (unsigned)__cvta_generic_to_shared(smem);
    asm volatile("cp.async.cg.shared.global [%0], [%1], 16;\n"
                 :: "r"(saddr), "l"(gmem));
}
__device__ __forceinline__ void cp_commit() {
    asm volatile("cp.async.commit_group;\n");
}
template<int N>
__device__ __forceinline__ void cp_wait() {
    asm volatile("cp.async.wait_group %0;\n" :: "n"(N));
}

// =============================================================================
// K-loop TF32 tensor GEMM: C = A(MxK) @ B(KxN) [+bias], 128x128 block tile,
// 4 warps (128 thr), 64x64 warp tile, BK=16, 4-stage cp.async pipeline.
// Raw fp32 staged in smem; cvt->tf32 at fragment load.
// OUTMODE 0: row-major C. OUTMODE 1: Q/K head-major scatter.
// =============================================================================
#define STAGES 4

template<int OUTMODE, bool BIAS>
__global__ void __launch_bounds__(128, 2) gemm_tc_kernel(
    const float* __restrict__ A, const float* __restrict__ B,
    float* __restrict__ C, const float* __restrict__ bias,
    int K, int lda, int ldb, int ldc,
    long long aStride, long long bStride, long long cStride)
{
    extern __shared__ float dsm[];
    float (*As)[128][20]  = (float(*)[128][20])dsm;
    float (*Bs)[16][136]  = (float(*)[16][136])(dsm + STAGES * 128 * 20);

    const int tid  = threadIdx.x;
    const int lane = tid & 31;
    const int wid  = tid >> 5;
    const int g = lane >> 2, t = lane & 3;
    const int m0 = (wid & 1) * 64;
    const int n0 = (wid >> 1) * 64;

    const float* Ab = A + (size_t)blockIdx.z * aStride + (size_t)blockIdx.y * 128 * lda;
    const float* Bb = B + (size_t)blockIdx.z * bStride + blockIdx.x * 128;
    float*       Cb = C + (size_t)blockIdx.z * cStride;

    const int arow = tid >> 2;          // 0..31 (+32*i)
    const int acol = (tid & 3) * 4;
    const int brow = tid >> 5;          // 0..3  (+4*i)
    const int bcol = (tid & 31) * 4;

    const int NKT = K / 16;

    auto issue = [&](int kt, int st) {
#pragma unroll
        for (int i = 0; i < 4; i++)
            cp_async16(&As[st][arow + 32 * i][acol],
                       Ab + (size_t)(arow + 32 * i) * lda + kt * 16 + acol);
#pragma unroll
        for (int i = 0; i < 4; i++)
            cp_async16(&Bs[st][brow + 4 * i][bcol],
                       Bb + (size_t)(kt * 16 + brow + 4 * i) * ldb + bcol);
        cp_commit();
    };

    // prologue: fill STAGES-1 stages
#pragma unroll
    for (int s = 0; s < STAGES - 1; ++s) issue(s, s);

    float acc[4][8][4];
#pragma unroll
    for (int mi = 0; mi < 4; mi++)
#pragma unroll
        for (int ni = 0; ni < 8; ni++)
#pragma unroll
            for (int r = 0; r < 4; r++) acc[mi][ni][r] = 0.f;

    for (int kt = 0; kt < NKT; ++kt) {
        cp_wait<STAGES - 2>();
        __syncthreads();
        const int buf = kt % STAGES;
        if (kt + STAGES - 1 < NKT) issue(kt + STAGES - 1, (kt + STAGES - 1) % STAGES);
        else cp_commit();   // keep group count advancing so wait_group drains

#pragma unroll
        for (int ks = 0; ks < 2; ++ks) {
            const int kb = ks * 8;
            unsigned a[4][4], b[8][2];
#pragma unroll
            for (int mi = 0; mi < 4; mi++) {
                int r = m0 + mi * 16 + g;
                a[mi][0] = f2tf(As[buf][r][kb + t]);
                a[mi][1] = f2tf(As[buf][r + 8][kb + t]);
                a[mi][2] = f2tf(As[buf][r][kb + 4 + t]);
                a[mi][3] = f2tf(As[buf][r + 8][kb + 4 + t]);
            }
#pragma unroll
            for (int ni = 0; ni < 8; ni++) {
                int cn = n0 + ni * 8 + g;
                b[ni][0] = f2tf(Bs[buf][kb + t][cn]);
                b[ni][1] = f2tf(Bs[buf][kb + 4 + t][cn]);
            }
#pragma unroll
            for (int mi = 0; mi < 4; mi++)
#pragma unroll
                for (int ni = 0; ni < 8; ni++)
                    mma_tf32(acc[mi][ni], a[mi][0], a[mi][1], a[mi][2], a[mi][3],
                             b[ni][0], b[ni][1]);
        }
        __syncthreads();
    }

    const int rbase = blockIdx.y * 128 + m0;
    const int cbase = blockIdx.x * 128 + n0;
#pragma unroll
    for (int mi = 0; mi < 4; mi++) {
#pragma unroll
        for (int ni = 0; ni < 8; ni++) {
            int r = rbase + mi * 16 + g;
            int c = cbase + ni * 8 + 2 * t;
            float2 v0 = { acc[mi][ni][0], acc[mi][ni][1] };
            float2 v1 = { acc[mi][ni][2], acc[mi][ni][3] };
            if (BIAS) {
                float2 bb = *(const float2*)&bias[c];
                v0.x += bb.x; v0.y += bb.y;
                v1.x += bb.x; v1.y += bb.y;
            }
            if (OUTMODE == 0) {
                *(float2*)&Cb[(size_t)r * ldc + c]       = v0;
                *(float2*)&Cb[(size_t)(r + 8) * ldc + c] = v1;
            } else {
                int b0i = r >> 11, q0 = r & 2047;
                int h = c >> 6, d = c & 63;
                *(float2*)&g_Q[0]; // no-op keep type
                float* base = Cb;  // Cb is the scatter target base
                *(float2*)&base[((size_t)((b0i * Hh + h) * Sq) + q0) * Dk + d] = v0;
                int r1 = r + 8;
                int b1i = r1 >> 11, q1 = r1 & 2047;
                *(float2*)&base[((size_t)((b1i * Hh + h) * Sq) + q1) * Dk + d] = v1;
            }
        }
    }
}

// =============================================================================
// Scores kernel (tensor): S = (1/8) * Q @ K^T per (b,h). K=64 fully in smem.
// 128 thr = 4 warps (2x2), warp tile 64x64, m16n8k8 tf32 (cvt at store).
// =============================================================================
__global__ void __launch_bounds__(128, 2) scores_tc_kernel(
    const float* __restrict__ Q, const float* __restrict__ K,
    float* __restrict__ S)
{
    extern __shared__ unsigned dynsmem[];
    unsigned (*Qs)[68] = (unsigned(*)[68])dynsmem;
    unsigned (*Ks)[68] = (unsigned(*)[68])(dynsmem + 128 * 68);

    const int tid  = threadIdx.x;
    const int lane = tid & 31;
    const int wid  = tid >> 5;
    const int g = lane >> 2, t = lane & 3;
    const int m0 = (wid & 1) * 64;
    const int n0 = (wid >> 1) * 64;

    const float* Qb = Q + (size_t)blockIdx.z * Sq * Dk + (size_t)blockIdx.y * 128 * Dk;
    const float* Kb = K + (size_t)blockIdx.z * Sq * Dk + (size_t)blockIdx.x * 128 * Dk;

#pragma unroll
    for (int i = 0; i < 16; ++i) {
        int idx = i * 128 + tid;          // 0..2047 float4 units
        int row = idx >> 4;
        int c4  = (idx & 15) * 4;
        float4 q = *(const float4*)&Qb[(size_t)row * Dk + c4];
        uint4 uq = { f2tf(q.x), f2tf(q.y), f2tf(q.z), f2tf(q.w) };
        *(uint4*)&Qs[row][c4] = uq;
        float4 k = *(const float4*)&Kb[(size_t)row * Dk + c4];
        uint4 uk = { f2tf(k.x), f2tf(k.y), f2tf(k.z), f2tf(k.w) };
        *(uint4*)&Ks[row][c4] = uk;
    }
    __syncthreads();

    float acc[4][8][4];
#pragma unroll
    for (int mi = 0; mi < 4; mi++)
#pragma unroll
        for (int ni = 0; ni < 8; ni++)
#pragma unroll
            for (int r = 0; r < 4; r++) acc[mi][ni][r] = 0.f;

#pragma unroll
    for (int ks = 0; ks < 8; ++ks) {
        const int kb = ks * 8;
        unsigned a[4][4], b[8][2];
#pragma unroll
        for (int mi = 0; mi < 4; mi++) {
            int r = m0 + mi * 16 + g;
            a[mi][0] = Qs[r][kb + t];
            a[mi][1] = Qs[r + 8][kb + t];
            a[mi][2] = Qs[r][kb + 4 + t];
            a[mi][3] = Qs[r + 8][kb + 4 + t];
        }
#pragma unroll
        for (int ni = 0; ni < 8; ni++) {
            int cn = n0 + ni * 8 + g;
            b[ni][0] = Ks[cn][kb + t];
            b[ni][1] = Ks[cn][kb + 4 + t];
        }
#pragma unroll
        for (int mi = 0; mi < 4; mi++)
#pragma unroll
            for (int ni = 0; ni < 8; ni++)
                mma_tf32(acc[mi][ni], a[mi][0], a[mi][1], a[mi][2], a[mi][3],
                         b[ni][0], b[ni][1]);
    }

    float* Sb = S + (size_t)blockIdx.z * Sq * Sq;
    const int rbase = blockIdx.y * 128 + m0;
    const int cbase = blockIdx.x * 128 + n0;
#pragma unroll
    for (int mi = 0; mi < 4; mi++) {
#pragma unroll
        for (int ni = 0; ni < 8; ni++) {
            int r = rbase + mi * 16 + g;
            int c = cbase + ni * 8 + 2 * t;
            float2 v0 = { acc[mi][ni][0] * 0.125f, acc[mi][ni][1] * 0.125f };
            float2 v1 = { acc[mi][ni][2] * 0.125f, acc[mi][ni][3] * 0.125f };
            *(float2*)&Sb[(size_t)r * Sq + c]       = v0;
            *(float2*)&Sb[(size_t)(r + 8) * Sq + c] = v1;
        }
    }
}

// =============================================================================
// Fused per-row softmax over 4 heads + head-average. Raw scores kept in smem;
// exp recomputed in the combine pass (MUFU is idle, L1 is the scarce pipe).
// =============================================================================
__device__ __forceinline__ float warp_max(float v) {
#pragma unroll
    for (int o = 16; o; o >>= 1) v = fmaxf(v, __shfl_xor_sync(0xffffffffu, v, o));
    return v;
}
__device__ __forceinline__ float warp_sum(float v) {
#pragma unroll
    for (int o = 16; o; o >>= 1) v += __shfl_xor_sync(0xffffffffu, v, o);
    return v;
}

__global__ void __launch_bounds__(256) softmax_avg_kernel(float* __restrict__ avg)
{
    const int q = blockIdx.x;
    const int b = blockIdx.y;
    __shared__ float sh[Hh][Sq];   // raw scores, 32KB
    __shared__ float red[8];

    const int tid  = threadIdx.x;
    const int lane = tid & 31;
    const int wid  = tid >> 5;

    float mh[Hh], rz[Hh];

#pragma unroll
    for (int h = 0; h < Hh; ++h) {
        const float* srow = &g_S[(((size_t)(b * Hh + h)) * Sq + q) * Sq];
        float lmax = -1e30f;
        for (int k = tid * 4; k < Sq; k += 1024) {
            float4 v = *(const float4*)&srow[k];
            *(float4*)&sh[h][k] = v;
            lmax = fmaxf(lmax, fmaxf(fmaxf(v.x, v.y), fmaxf(v.z, v.w)));
        }
        float wm = warp_max(lmax);
        if (lane == 0) red[wid] = wm;
        __syncthreads();
        float m = red[0];
#pragma unroll
        for (int i = 1; i < 8; i++) m = fmaxf(m, red[i]);
        __syncthreads();
        float lsum = 0.f;
        for (int k = tid * 4; k < Sq; k += 1024) {
            float4 v = *(const float4*)&sh[h][k];
            lsum += (__expf(v.x - m) + __expf(v.y - m)) +
                    (__expf(v.z - m) + __expf(v.w - m));
        }
        float ws = warp_sum(lsum);
        if (lane == 0) red[wid] = ws;
        __syncthreads();
        float zt = red[0];
#pragma unroll
        for (int i = 1; i < 8; i++) zt += red[i];
        __syncthreads();
        mh[h] = m;
        rz[h] = 0.25f / zt;
    }

    float* orow = &avg[((size_t)b * Sq + q) * Sq];
    for (int k = tid * 4; k < Sq; k += 1024) {
        float4 r = {0.f, 0.f, 0.f, 0.f};
#pragma unroll
        for (int h = 0; h < Hh; ++h) {
            float4 v = *(const float4*)&sh[h][k];
            r.x += __expf(v.x - mh[h]) * rz[h];
            r.y += __expf(v.y - mh[h]) * rz[h];
            r.z += __expf(v.z - mh[h]) * rz[h];
            r.w += __expf(v.w - mh[h]) * rz[h];
        }
        *(float4*)&orow[k] = r;
    }
}

// =============================================================================
// Launch
// =============================================================================
extern "C" void kernel_launch(void* const* d_in, const int* in_sizes, int n_in,
                              void* d_out, int out_size)
{
    (void)in_sizes; (void)n_in; (void)out_size;
    const float* query = (const float*)d_in[0];
    const float* key   = (const float*)d_in[1];
    const float* value = (const float*)d_in[2];
    const float* W_q   = (const float*)d_in[3];
    const float* b_q   = (const float*)d_in[4];
    const float* W_k   = (const float*)d_in[5];
    const float* b_k   = (const float*)d_in[6];
    const float* W_v   = (const float*)d_in[7];
    const float* b_v   = (const float*)d_in[8];
    const float* W_o   = (const float*)d_in[9];
    const float* b_o   = (const float*)d_in[10];

    float* out = (float*)d_out;                 // (B,S,D)
    float* avg = out + OUT0_ELEMS;              // (B,S,S)

    float *pQ, *pK, *pV, *pS, *pO;
    cudaGetSymbolAddress((void**)&pQ, g_Q);
    cudaGetSymbolAddress((void**)&pK, g_K);
    cudaGetSymbolAddress((void**)&pV, g_V);
    cudaGetSymbolAddress((void**)&pS, g_S);
    cudaGetSymbolAddress((void**)&pO, g_O);

    const int gemm_smem = (STAGES * 128 * 20 + STAGES * 16 * 136) * 4; // 75776 B
    cudaFuncSetAttribute(gemm_tc_kernel<1, true>,
        cudaFuncAttributeMaxDynamicSharedMemorySize, gemm_smem);
    cudaFuncSetAttribute(gemm_tc_kernel<0, true>,
        cudaFuncAttributeMaxDynamicSharedMemorySize, gemm_smem);
    cudaFuncSetAttribute(gemm_tc_kernel<0, false>,
        cudaFuncAttributeMaxDynamicSharedMemorySize, gemm_smem);

    dim3 blk128(128);

    // 1-3: input projections (tensor tf32, K=256)
    {
        dim3 grid(Dm / 128, NTOK / 128, 1);
        gemm_tc_kernel<1, true><<<grid, blk128, gemm_smem>>>(query, W_q, pQ, b_q,
            Dm, Dm, Dm, Dm, 0, 0, 0);
        gemm_tc_kernel<1, true><<<grid, blk128, gemm_smem>>>(key, W_k, pK, b_k,
            Dm, Dm, Dm, Dm, 0, 0, 0);
        gemm_tc_kernel<0, true><<<grid, blk128, gemm_smem>>>(value, W_v, pV, b_v,
            Dm, Dm, Dm, Dm, 0, 0, 0);
    }

    // 4: scores S = (1/8) * Q @ K^T per (b,h)
    {
        const int smem = 2 * 128 * 68 * 4;   // 69632 B
        cudaFuncSetAttribute(scores_tc_kernel,
            cudaFuncAttributeMaxDynamicSharedMemorySize, smem);
        dim3 grid(Sq / 128, Sq / 128, Bsz * Hh);
        scores_tc_kernel<<<grid, blk128, smem>>>(pQ, pK, pS);
    }

    // 5: softmax per head + average over heads -> avg_attn (in d_out)
    {
        dim3 grid(Sq, Bsz, 1);
        softmax_avg_kernel<<<grid, 256>>>(avg);
    }

    // 6: out_pre = avg_attn @ V per batch (tensor tf32, K=2048)
    {
        dim3 grid(Dm / 128, Sq / 128, Bsz);
        gemm_tc_kernel<0, false><<<grid, blk128, gemm_smem>>>(avg, pV, pO, nullptr,
            Sq, Sq, Dm, Dm,
            (long long)Sq * Sq, (long long)Sq * Dm, (long long)Sq * Dm);
    }

    // 7: final projection out = out_pre @ W_o + b_o (tensor tf32)
    {
        dim3 grid(Dm / 128, NTOK / 128, 1);
        gemm_tc_kernel<0, true><<<grid, blk128, gemm_smem>>>(pO, W_o, out, b_o,
            Dm, Dm, Dm, Dm, 0, 0, 0);
    }
}

// round 4
// speedup vs baseline: 4.2925x; 1.2594x over previous
#include <cuda_runtime.h>
#include <math.h>

// Problem constants
#define Bsz 8
#define Sq  2048
#define Dm  256
#define Hh  4
#define Dk  64
#define NTOK (Bsz*Sq)          // 16384
#define OUT0_ELEMS ((size_t)NTOK*Dm) // 4194304
#define NROWS (Bsz*Hh*Sq)      // 65536 (b,h,q) rows
#define NXT 16                 // k-tiles per score row (2048/128)

// ---------------- scratch (static device globals; allocation-free contract) ---
__device__ float g_Q[(size_t)Bsz*Hh*Sq*Dk];   // (b,h,q,d) 16MB
__device__ float g_K[(size_t)Bsz*Hh*Sq*Dk];   // 16MB
__device__ float g_V[(size_t)NTOK*Dm];        // 16MB
__device__ float g_E[(size_t)Bsz*Hh*Sq*Sq];   // exp(scores), 512MiB
__device__ float g_O[(size_t)NTOK*Dm];        // attn output pre-proj, 16MB
__device__ float g_Zp[(size_t)NXT*NROWS];     // per-k-tile row-sum partials, 4MB
__device__ float g_RZ[(size_t)NROWS];         // 0.25 / rowsum

// =============================================================================
// helpers
// =============================================================================
__device__ __forceinline__ unsigned f2tf(float f) {
    unsigned u;
    asm("cvt.rna.tf32.f32 %0, %1;" : "=r"(u) : "f"(f));
    return u;
}
__device__ __forceinline__ void mma_tf32(float c[4],
    unsigned a0, unsigned a1, unsigned a2, unsigned a3,
    unsigned b0, unsigned b1)
{
    asm volatile(
        "mma.sync.aligned.m16n8k8.row.col.f32.tf32.tf32.f32 "
        "{%0,%1,%2,%3},{%4,%5,%6,%7},{%8,%9},{%0,%1,%2,%3};"
        : "+f"(c[0]), "+f"(c[1]), "+f"(c[2]), "+f"(c[3])
        : "r"(a0), "r"(a1), "r"(a2), "r"(a3), "r"(b0), "r"(b1));
}
__device__ __forceinline__ void cp_async16(void* smem, const void* gmem) {
    unsigned saddr = (unsigned)__cvta_generic_to_shared(smem);
    asm volatile("cp.async.cg.shared.global [%0], [%1], 16;\n"
                 :: "r"(saddr), "l"(gmem));
}
__device__ __forceinline__ void cp_commit() {
    asm volatile("cp.async.commit_group;\n");
}
template<int N>
__device__ __forceinline__ void cp_wait() {
    asm volatile("cp.async.wait_group %0;\n" :: "n"(N));
}

// =============================================================================
// K-loop TF32 tensor GEMM (projections + final): 128x128 block, 4 warps,
// 64x64 warp tile, BK=16, 4-stage cp.async. OUTMODE 1 = Q/K head scatter.
// =============================================================================
#define STAGES 4

template<int OUTMODE, bool BIAS>
__global__ void __launch_bounds__(128, 2) gemm_tc_kernel(
    const float* __restrict__ A, const float* __restrict__ B,
    float* __restrict__ C, const float* __restrict__ bias,
    int K, int lda, int ldb, int ldc)
{
    extern __shared__ float dsm[];
    float (*As)[128][20]  = (float(*)[128][20])dsm;
    float (*Bs)[16][136]  = (float(*)[16][136])(dsm + STAGES * 128 * 20);

    const int tid  = threadIdx.x;
    const int lane = tid & 31;
    const int wid  = tid >> 5;
    const int g = lane >> 2, t = lane & 3;
    const int m0 = (wid & 1) * 64;
    const int n0 = (wid >> 1) * 64;

    const float* Ab = A + (size_t)blockIdx.y * 128 * lda;
    const float* Bb = B + blockIdx.x * 128;
    float*       Cb = C;

    const int arow = tid >> 2;
    const int acol = (tid & 3) * 4;
    const int brow = tid >> 5;
    const int bcol = (tid & 31) * 4;

    const int NKT = K / 16;

    auto issue = [&](int kt, int st) {
#pragma unroll
        for (int i = 0; i < 4; i++)
            cp_async16(&As[st][arow + 32 * i][acol],
                       Ab + (size_t)(arow + 32 * i) * lda + kt * 16 + acol);
#pragma unroll
        for (int i = 0; i < 4; i++)
            cp_async16(&Bs[st][brow + 4 * i][bcol],
                       Bb + (size_t)(kt * 16 + brow + 4 * i) * ldb + bcol);
        cp_commit();
    };

#pragma unroll
    for (int s = 0; s < STAGES - 1; ++s) issue(s, s);

    float acc[4][8][4];
#pragma unroll
    for (int mi = 0; mi < 4; mi++)
#pragma unroll
        for (int ni = 0; ni < 8; ni++)
#pragma unroll
            for (int r = 0; r < 4; r++) acc[mi][ni][r] = 0.f;

    for (int kt = 0; kt < NKT; ++kt) {
        cp_wait<STAGES - 2>();
        __syncthreads();
        const int buf = kt % STAGES;
        if (kt + STAGES - 1 < NKT) issue(kt + STAGES - 1, (kt + STAGES - 1) % STAGES);
        else cp_commit();

#pragma unroll
        for (int ks = 0; ks < 2; ++ks) {
            const int kb = ks * 8;
            unsigned a[4][4], b[8][2];
#pragma unroll
            for (int mi = 0; mi < 4; mi++) {
                int r = m0 + mi * 16 + g;
                a[mi][0] = f2tf(As[buf][r][kb + t]);
                a[mi][1] = f2tf(As[buf][r + 8][kb + t]);
                a[mi][2] = f2tf(As[buf][r][kb + 4 + t]);
                a[mi][3] = f2tf(As[buf][r + 8][kb + 4 + t]);
            }
#pragma unroll
            for (int ni = 0; ni < 8; ni++) {
                int cn = n0 + ni * 8 + g;
                b[ni][0] = f2tf(Bs[buf][kb + t][cn]);
                b[ni][1] = f2tf(Bs[buf][kb + 4 + t][cn]);
            }
#pragma unroll
            for (int mi = 0; mi < 4; mi++)
#pragma unroll
                for (int ni = 0; ni < 8; ni++)
                    mma_tf32(acc[mi][ni], a[mi][0], a[mi][1], a[mi][2], a[mi][3],
                             b[ni][0], b[ni][1]);
        }
        __syncthreads();
    }

    const int rbase = blockIdx.y * 128 + m0;
    const int cbase = blockIdx.x * 128 + n0;
#pragma unroll
    for (int mi = 0; mi < 4; mi++) {
#pragma unroll
        for (int ni = 0; ni < 8; ni++) {
            int r = rbase + mi * 16 + g;
            int c = cbase + ni * 8 + 2 * t;
            float2 v0 = { acc[mi][ni][0], acc[mi][ni][1] };
            float2 v1 = { acc[mi][ni][2], acc[mi][ni][3] };
            if (BIAS) {
                float2 bb = *(const float2*)&bias[c];
                v0.x += bb.x; v0.y += bb.y;
                v1.x += bb.x; v1.y += bb.y;
            }
            if (OUTMODE == 0) {
                *(float2*)&Cb[(size_t)r * ldc + c]       = v0;
                *(float2*)&Cb[(size_t)(r + 8) * ldc + c] = v1;
            } else {
                int b0i = r >> 11, q0 = r & 2047;
                int h = c >> 6, d = c & 63;
                *(float2*)&Cb[((size_t)((b0i * Hh + h) * Sq) + q0) * Dk + d] = v0;
                int r1 = r + 8;
                int b1i = r1 >> 11, q1 = r1 & 2047;
                *(float2*)&Cb[((size_t)((b1i * Hh + h) * Sq) + q1) * Dk + d] = v1;
            }
        }
    }
}

// =============================================================================
// Scores kernel: E = exp((Q@K^T)/8) per (b,h); also per-CTA row-sum partials.
// 256 thr, 8 warps (2m x 4n), warp tile 64x32, K=64 fully staged.
// =============================================================================
__global__ void __launch_bounds__(256, 2) scores_tc_kernel(
    const float* __restrict__ Q, const float* __restrict__ K,
    float* __restrict__ E, float* __restrict__ Zp)
{
    extern __shared__ unsigned dynsmem[];
    unsigned (*Qs)[68] = (unsigned(*)[68])dynsmem;
    unsigned (*Ks)[68] = (unsigned(*)[68])(dynsmem + 128 * 68);
    __shared__ float wsum[4][128];

    const int tid  = threadIdx.x;
    const int lane = tid & 31;
    const int wid  = tid >> 5;
    const int g = lane >> 2, t = lane & 3;
    const int m0 = (wid & 1) * 64;
    const int n0 = (wid >> 1) * 32;
    const int nwid = wid >> 1;

    const float* Qb = Q + (size_t)blockIdx.z * Sq * Dk + (size_t)blockIdx.y * 128 * Dk;
    const float* Kb = K + (size_t)blockIdx.z * Sq * Dk + (size_t)blockIdx.x * 128 * Dk;

#pragma unroll
    for (int i = 0; i < 8; ++i) {
        int idx = i * 256 + tid;
        int row = idx >> 4;
        int c4  = (idx & 15) * 4;
        float4 q = *(const float4*)&Qb[(size_t)row * Dk + c4];
        uint4 uq = { f2tf(q.x), f2tf(q.y), f2tf(q.z), f2tf(q.w) };
        *(uint4*)&Qs[row][c4] = uq;
        float4 k = *(const float4*)&Kb[(size_t)row * Dk + c4];
        uint4 uk = { f2tf(k.x), f2tf(k.y), f2tf(k.z), f2tf(k.w) };
        *(uint4*)&Ks[row][c4] = uk;
    }
    __syncthreads();

    float acc[4][4][4];
#pragma unroll
    for (int mi = 0; mi < 4; mi++)
#pragma unroll
        for (int ni = 0; ni < 4; ni++)
#pragma unroll
            for (int r = 0; r < 4; r++) acc[mi][ni][r] = 0.f;

#pragma unroll
    for (int ks = 0; ks < 8; ++ks) {
        const int kb = ks * 8;
        unsigned a[4][4], b[4][2];
#pragma unroll
        for (int mi = 0; mi < 4; mi++) {
            int r = m0 + mi * 16 + g;
            a[mi][0] = Qs[r][kb + t];
            a[mi][1] = Qs[r + 8][kb + t];
            a[mi][2] = Qs[r][kb + 4 + t];
            a[mi][3] = Qs[r + 8][kb + 4 + t];
        }
#pragma unroll
        for (int ni = 0; ni < 4; ni++) {
            int cn = n0 + ni * 8 + g;
            b[ni][0] = Ks[cn][kb + t];
            b[ni][1] = Ks[cn][kb + 4 + t];
        }
#pragma unroll
        for (int mi = 0; mi < 4; mi++)
#pragma unroll
            for (int ni = 0; ni < 4; ni++)
                mma_tf32(acc[mi][ni], a[mi][0], a[mi][1], a[mi][2], a[mi][3],
                         b[ni][0], b[ni][1]);
    }

    // epilogue: e = exp(s/8), store E, accumulate row-sum partials
    float* Eb = E + (size_t)blockIdx.z * Sq * Sq;
    const int rbase = blockIdx.y * 128 + m0;
    const int cbase = blockIdx.x * 128 + n0;
#pragma unroll
    for (int mi = 0; mi < 4; mi++) {
        float s0 = 0.f, s1 = 0.f;
        int r = rbase + mi * 16 + g;
#pragma unroll
        for (int ni = 0; ni < 4; ni++) {
            int c = cbase + ni * 8 + 2 * t;
            float e00 = __expf(acc[mi][ni][0] * 0.125f);
            float e01 = __expf(acc[mi][ni][1] * 0.125f);
            float e10 = __expf(acc[mi][ni][2] * 0.125f);
            float e11 = __expf(acc[mi][ni][3] * 0.125f);
            float2 v0 = { e00, e01 };
            float2 v1 = { e10, e11 };
            *(float2*)&Eb[(size_t)r * Sq + c]       = v0;
            *(float2*)&Eb[(size_t)(r + 8) * Sq + c] = v1;
            s0 += e00 + e01;
            s1 += e10 + e11;
        }
        s0 += __shfl_xor_sync(0xffffffffu, s0, 1);
        s0 += __shfl_xor_sync(0xffffffffu, s0, 2);
        s1 += __shfl_xor_sync(0xffffffffu, s1, 1);
        s1 += __shfl_xor_sync(0xffffffffu, s1, 2);
        if (t == 0) {
            wsum[nwid][m0 + mi * 16 + g]     = s0;
            wsum[nwid][m0 + mi * 16 + g + 8] = s1;
        }
    }
    __syncthreads();
    if (tid < 128) {
        float zp = (wsum[0][tid] + wsum[1][tid]) + (wsum[2][tid] + wsum[3][tid]);
        Zp[(size_t)blockIdx.x * NROWS + (size_t)blockIdx.z * Sq
           + blockIdx.y * 128 + tid] = zp;
    }
}

// =============================================================================
// Z reduce: RZ[row] = 0.25 / sum_x Zp[x][row]  (fixed order -> deterministic)
// =============================================================================
__global__ void __launch_bounds__(256) zred_kernel(
    const float* __restrict__ Zp, float* __restrict__ RZ)
{
    int i = blockIdx.x * 256 + threadIdx.x;
    float s = 0.f;
#pragma unroll
    for (int x = 0; x < NXT; x++) s += Zp[(size_t)x * NROWS + i];
    RZ[i] = 0.25f / s;
}

// =============================================================================
// Fused avg + avg@V: per batch, block tile 128(q) x 256(full Dm), BK=16.
// A-tile = 0.25 * sum_h E_h * rz_h  computed on the fly from 4 E planes;
// written BOTH to d_out avg region and to smem for the MMA.
// 256 thr, 8 warps (2m x 4n), warp tile 64x64.
// smem layout (floats): rzs[128*4] | As[2][128][20] | Bs[2][16][264]
// =============================================================================
#define AV_RZ 0
#define AV_AS 512
#define AV_BS (512 + 2*128*20)
#define AV_SMEM_FLOATS (512 + 2*128*20 + 2*16*264)

__global__ void __launch_bounds__(256, 1) avgv_fused_kernel(
    const float* __restrict__ E, const float* __restrict__ RZ,
    const float* __restrict__ V, float* __restrict__ avg,
    float* __restrict__ Opre)
{
    extern __shared__ float sm[];
    float* rzs = sm + AV_RZ;                       // [row][h] : row*4+h
    float (*As)[128][20]  = (float(*)[128][20])(sm + AV_AS);
    float (*Bs)[16][264]  = (float(*)[16][264])(sm + AV_BS);

    const int tid  = threadIdx.x;
    const int lane = tid & 31;
    const int wid  = tid >> 5;
    const int g = lane >> 2, t = lane & 3;
    const int m0 = (wid & 1) * 64;
    const int n0 = (wid >> 1) * 64;

    const int b  = blockIdx.z;
    const int qb = blockIdx.y * 128;

    const float* Ep[Hh];
#pragma unroll
    for (int h = 0; h < Hh; h++)
        Ep[h] = E + ((size_t)(b * Hh + h) * Sq + qb) * Sq;
    const float* Vb = V + (size_t)b * Sq * Dm;
    float* avgb = avg + ((size_t)b * Sq + qb) * Sq;

    // rz staging
    for (int i = tid; i < 512; i += 256) {
        int h = i & 3, row = i >> 2;
        rzs[row * 4 + h] = RZ[(size_t)(b * Hh + h) * Sq + qb + row];
    }

    const int arow = tid >> 2;           // 0..63 (+64)
    const int acol = (tid & 3) * 4;
    const int brow = tid >> 4;           // 0..15
    const int bcolb = (tid & 15) * 4;

    float4 pa[Hh][2];

    auto loadA = [&](int kt) {
#pragma unroll
        for (int h = 0; h < Hh; h++) {
            pa[h][0] = *(const float4*)&Ep[h][(size_t)arow * Sq + kt * 16 + acol];
            pa[h][1] = *(const float4*)&Ep[h][(size_t)(arow + 64) * Sq + kt * 16 + acol];
        }
    };
    auto issueB = [&](int kt, int buf) {
#pragma unroll
        for (int j = 0; j < 4; j++)
            cp_async16(&Bs[buf][brow][bcolb + j * 64],
                       Vb + (size_t)(kt * 16 + brow) * Dm + bcolb + j * 64);
        cp_commit();
    };
    auto storeA = [&](int buf, int kt) {
        float rz0[Hh], rz1[Hh];
#pragma unroll
        for (int h = 0; h < Hh; h++) {
            rz0[h] = rzs[arow * 4 + h];
            rz1[h] = rzs[(arow + 64) * 4 + h];
        }
        float4 c0 = {0,0,0,0}, c1 = {0,0,0,0};
#pragma unroll
        for (int h = 0; h < Hh; h++) {
            c0.x += pa[h][0].x * rz0[h]; c0.y += pa[h][0].y * rz0[h];
            c0.z += pa[h][0].z * rz0[h]; c0.w += pa[h][0].w * rz0[h];
            c1.x += pa[h][1].x * rz1[h]; c1.y += pa[h][1].y * rz1[h];
            c1.z += pa[h][1].z * rz1[h]; c1.w += pa[h][1].w * rz1[h];
        }
        *(float4*)&avgb[(size_t)arow * Sq + kt * 16 + acol]        = c0;
        *(float4*)&avgb[(size_t)(arow + 64) * Sq + kt * 16 + acol] = c1;
        *(float4*)&As[buf][arow][acol]      = c0;
        *(float4*)&As[buf][arow + 64][acol] = c1;
    };

    float acc[4][8][4];
#pragma unroll
    for (int mi = 0; mi < 4; mi++)
#pragma unroll
        for (int ni = 0; ni < 8; ni++)
#pragma unroll
            for (int r = 0; r < 4; r++) acc[mi][ni][r] = 0.f;

    loadA(0);
    issueB(0, 0);
    __syncthreads();            // rzs visible
    storeA(0, 0);
    cp_wait<0>();
    __syncthreads();

    const int NKT = Sq / 16;    // 128
    for (int kt = 0; kt < NKT; ++kt) {
        const int buf = kt & 1;
        if (kt + 1 < NKT) {
            loadA(kt + 1);
            issueB(kt + 1, buf ^ 1);
        }

#pragma unroll
        for (int ks = 0; ks < 2; ++ks) {
            const int kb = ks * 8;
            unsigned a[4][4], bb[8][2];
#pragma unroll
            for (int mi = 0; mi < 4; mi++) {
                int r = m0 + mi * 16 + g;
                a[mi][0] = f2tf(As[buf][r][kb + t]);
                a[mi][1] = f2tf(As[buf][r + 8][kb + t]);
                a[mi][2] = f2tf(As[buf][r][kb + 4 + t]);
                a[mi][3] = f2tf(As[buf][r + 8][kb + 4 + t]);
            }
#pragma unroll
            for (int ni = 0; ni < 8; ni++) {
                int cn = n0 + ni * 8 + g;
                bb[ni][0] = f2tf(Bs[buf][kb + t][cn]);
                bb[ni][1] = f2tf(Bs[buf][kb + 4 + t][cn]);
            }
#pragma unroll
            for (int mi = 0; mi < 4; mi++)
#pragma unroll
                for (int ni = 0; ni < 8; ni++)
                    mma_tf32(acc[mi][ni], a[mi][0], a[mi][1], a[mi][2], a[mi][3],
                             bb[ni][0], bb[ni][1]);
        }

        if (kt + 1 < NKT) {
            storeA(buf ^ 1, kt + 1);
            cp_wait<0>();
        }
        __syncthreads();
    }

    float* Ob = Opre + (size_t)b * Sq * Dm;
    const int rbase = qb + m0;
    const int cbase = n0;
#pragma unroll
    for (int mi = 0; mi < 4; mi++) {
#pragma unroll
        for (int ni = 0; ni < 8; ni++) {
            int r = rbase + mi * 16 + g;
            int c = cbase + ni * 8 + 2 * t;
            float2 v0 = { acc[mi][ni][0], acc[mi][ni][1] };
            float2 v1 = { acc[mi][ni][2], acc[mi][ni][3] };
            *(float2*)&Ob[(size_t)r * Dm + c]       = v0;
            *(float2*)&Ob[(size_t)(r + 8) * Dm + c] = v1;
        }
    }
}

// =============================================================================
// Launch
// =============================================================================
extern "C" void kernel_launch(void* const* d_in, const int* in_sizes, int n_in,
                              void* d_out, int out_size)
{
    (void)in_sizes; (void)n_in; (void)out_size;
    const float* query = (const float*)d_in[0];
    const float* key   = (const float*)d_in[1];
    const float* value = (const float*)d_in[2];
    const float* W_q   = (const float*)d_in[3];
    const float* b_q   = (const float*)d_in[4];
    const float* W_k   = (const float*)d_in[5];
    const float* b_k   = (const float*)d_in[6];
    const float* W_v   = (const float*)d_in[7];
    const float* b_v   = (const float*)d_in[8];
    const float* W_o   = (const float*)d_in[9];
    const float* b_o   = (const float*)d_in[10];

    float* out = (float*)d_out;                 // (B,S,D)
    float* avg = out + OUT0_ELEMS;              // (B,S,S)

    float *pQ, *pK, *pV, *pE, *pO, *pZp, *pRZ;
    cudaGetSymbolAddress((void**)&pQ,  g_Q);
    cudaGetSymbolAddress((void**)&pK,  g_K);
    cudaGetSymbolAddress((void**)&pV,  g_V);
    cudaGetSymbolAddress((void**)&pE,  g_E);
    cudaGetSymbolAddress((void**)&pO,  g_O);
    cudaGetSymbolAddress((void**)&pZp, g_Zp);
    cudaGetSymbolAddress((void**)&pRZ, g_RZ);

    const int gemm_smem = (STAGES * 128 * 20 + STAGES * 16 * 136) * 4;
    cudaFuncSetAttribute(gemm_tc_kernel<1, true>,
        cudaFuncAttributeMaxDynamicSharedMemorySize, gemm_smem);
    cudaFuncSetAttribute(gemm_tc_kernel<0, true>,
        cudaFuncAttributeMaxDynamicSharedMemorySize, gemm_smem);

    // 1-3: input projections
    {
        dim3 grid(Dm / 128, NTOK / 128, 1);
        gemm_tc_kernel<1, true><<<grid, 128, gemm_smem>>>(query, W_q, pQ, b_q,
            Dm, Dm, Dm, Dm);
        gemm_tc_kernel<1, true><<<grid, 128, gemm_smem>>>(key, W_k, pK, b_k,
            Dm, Dm, Dm, Dm);
        gemm_tc_kernel<0, true><<<grid, 128, gemm_smem>>>(value, W_v, pV, b_v,
            Dm, Dm, Dm, Dm);
    }

    // 4: E = exp(Q@K^T / 8) + row-sum partials
    {
        const int smem = 2 * 128 * 68 * 4;   // 69632 B
        cudaFuncSetAttribute(scores_tc_kernel,
            cudaFuncAttributeMaxDynamicSharedMemorySize, smem);
        dim3 grid(Sq / 128, Sq / 128, Bsz * Hh);
        scores_tc_kernel<<<grid, 256, smem>>>(pQ, pK, pE, pZp);
    }

    // 5: deterministic Z reduce -> 0.25/Z
    zred_kernel<<<NROWS / 256, 256>>>(pZp, pRZ);

    // 6: fused avg_attn production + avg@V
    {
        const int smem = AV_SMEM_FLOATS * 4;  // 56320 B
        cudaFuncSetAttribute(avgv_fused_kernel,
            cudaFuncAttributeMaxDynamicSharedMemorySize, smem);
        dim3 grid(1, Sq / 128, Bsz);
        avgv_fused_kernel<<<grid, 256, smem>>>(pE, pRZ, pV, avg, pO);
    }

    // 7: final projection out = out_pre @ W_o + b_o
    {
        dim3 grid(Dm / 128, NTOK / 128, 1);
        gemm_tc_kernel<0, true><<<grid, 128, gemm_smem>>>(pO, W_o, out, b_o,
            Dm, Dm, Dm, Dm);
    }
}